// round 5
// baseline (speedup 1.0000x reference)
#include <cuda_runtime.h>
#include <cstdint>

#define DEV_INLINE __device__ __forceinline__

constexpr int N  = 256;
constexpr int T  = 1024;
constexpr int P  = 4;
constexpr int AS = T + P;        // alpha row stride = 1028
constexpr int Tp = T - P;        // 1020

// ---- btl tiling: block = (tile-pair, t-half) = 8i x 8j x 512t ----
constexpr int TI     = 8;
constexpr int NTILE  = N / TI;                  // 32
constexpr int TPAIRS = NTILE * (NTILE + 1) / 2; // 528
constexpr int THALVES = 2;                      // 512 t each
constexpr int TT     = 256;                     // t per chunk (= blockDim)
constexpr int BTL_BLOCKS = TPAIRS * THALVES;    // 1056

// ---- ar tiling ----
constexpr int AR_TT     = 8;
constexpr int AR_BLOCKS = (Tp + AR_TT - 1) / AR_TT; // 128

constexpr int TOTAL_BLOCKS = BTL_BLOCKS + AR_BLOCKS; // 1184 = 2 waves @ occ 4

__device__ float  g_btl_partial[BTL_BLOCKS];
__device__ double g_ar_partial[AR_BLOCKS];
__device__ float  g_phiT[P * N * N];  // PhiT[k][m][n]

struct SmemBTL {
    float red[8];
};
struct SmemAR {
    float sa[N][AR_TT + P];
    float red[8];
};
union SmemU { SmemBTL b; SmemAR a; };

DEV_INLINE float warpReduce(float v) {
    #pragma unroll
    for (int o = 16; o > 0; o >>= 1)
        v += __shfl_xor_sync(0xffffffffu, v, o);
    return v;
}

DEV_INLINE float blockReduce(float v, float* red) {
    v = warpReduce(v);
    if ((threadIdx.x & 31) == 0) red[threadIdx.x >> 5] = v;
    __syncthreads();
    float r = 0.f;
    if (threadIdx.x < 32) {
        r = (threadIdx.x < 8) ? red[threadIdx.x] : 0.f;
        #pragma unroll
        for (int o = 4; o > 0; o >>= 1)
            r += __shfl_xor_sync(0xffffffffu, r, o);
    }
    __syncthreads();
    return r;
}

// ---------------- BTL part ----------------
// One chunk: 8x8 pairs x 256 t, register-staged alpha, single code path
// (diagonal handled by a 0/1 mask that only costs on lower-triangle iters).
DEV_INLINE void btl_chunk(const float* __restrict__ Z,
                          const float* __restrict__ W,
                          const float* __restrict__ alpha,
                          int i0, int j0, int t0, bool diag,
                          float& acc0, float& acc1) {
    const int tid = threadIdx.x;

    float si[TI], ei[TI], sj[TI], ej[TI];
    #pragma unroll
    for (int r = 0; r < TI; ++r) {
        si[r] = alpha[(i0 + r) * AS + P + t0 + tid];
        sj[r] = alpha[(j0 + r) * AS + P + t0 + tid];
    }
    #pragma unroll
    for (int r = 0; r < TI; ++r) {
        ei[r] = __expf(si[r]);
        ej[r] = __expf(sj[r]);
    }

    const float dm = diag ? 0.f : 1.f;
    const size_t base = ((size_t)i0 * N + j0) * T + t0 + tid;

    #pragma unroll
    for (int pi = 0; pi < TI; ++pi) {
        const float* zr = Z + base + (size_t)pi * N * T;
        const float* wr = W + base + (size_t)pi * N * T;

        // batched independent loads -> high MLP, 1-KB bursts per (i,j) row
        float z[TI], w[TI];
        #pragma unroll
        for (int pj = 0; pj < TI; ++pj) z[pj] = zr[(size_t)pj * T];
        #pragma unroll
        for (int pj = 0; pj < TI; ++pj) w[pj] = wr[(size_t)pj * T];

        #pragma unroll
        for (int pj = 0; pj < TI; ++pj) {
            float lse = __logf(ei[pi] + ej[pj]);
            if (pj <= pi) {       // compile-time: mask only lower triangle + diag
                acc0 = fmaf(z[pj] * dm, si[pi] - lse, acc0);
                acc1 = fmaf(w[pj] * dm, sj[pj] - lse, acc1);
            } else {
                acc0 = fmaf(z[pj], si[pi] - lse, acc0);
                acc1 = fmaf(w[pj], sj[pj] - lse, acc1);
            }
        }
    }
}

DEV_INLINE void btl_block(const float* __restrict__ Z,
                          const float* __restrict__ W,
                          const float* __restrict__ alpha,
                          SmemBTL& s, int bid) {
    const int thalf = bid & 1;
    int tp = bid >> 1;                  // tile-pair index 0..527
    int it = 0;
    #pragma unroll 1
    while (tp >= NTILE - it) { tp -= NTILE - it; ++it; }
    const int jt = it + tp;

    const int i0 = it * TI, j0 = jt * TI;
    const bool diag = (it == jt);

    float acc0 = 0.f, acc1 = 0.f;
    #pragma unroll 1
    for (int c = 0; c < 2; ++c) {
        const int t0 = thalf * 512 + c * TT;
        btl_chunk(Z, W, alpha, i0, j0, t0, diag, acc0, acc1);
    }

    float tot = blockReduce(acc0 + acc1, s.red);
    if (threadIdx.x == 0) g_btl_partial[bid] = tot;
}

// ---------------- AR part (proven, unchanged) ----------------
DEV_INLINE void ar_block(const float* __restrict__ alpha,
                         SmemAR& s, int abid) {
    const int t0  = abid * AR_TT;
    const int tid = threadIdx.x;   // = n

    #pragma unroll
    for (int c = 0; c < AR_TT + P; ++c)
        s.sa[tid][c] = alpha[tid * AS + t0 + c];
    __syncthreads();

    float acc[AR_TT];
    #pragma unroll
    for (int tt = 0; tt < AR_TT; ++tt) acc[tt] = 0.f;

    #pragma unroll 2
    for (int m = 0; m < N; ++m) {
        float av[AR_TT + P];
        #pragma unroll
        for (int c = 0; c < AR_TT + P; ++c) av[c] = s.sa[m][c];
        #pragma unroll
        for (int k = 0; k < P; ++k) {
            float phi = g_phiT[((k * N) + m) * N + tid]; // coalesced over tid
            #pragma unroll
            for (int tt = 0; tt < AR_TT; ++tt)
                acc[tt] = fmaf(phi, av[k + tt], acc[tt]);
        }
    }

    // sum_{n,n2} (S_n - A_n2)^2 = N*sum S^2 - 2*(sum S)(sum A) + N*sum A^2
    double part = 0.0;
    #pragma unroll 1
    for (int tt = 0; tt < AR_TT; ++tt) {
        float S = acc[tt];
        float A = s.sa[tid][tt + P];
        float s1 = blockReduce(S, s.red);
        float s2 = blockReduce(S * S, s.red);
        float a1 = blockReduce(A, s.red);
        float a2 = blockReduce(A * A, s.red);
        if (tid == 0 && (t0 + tt) < Tp) {
            part += (double)N * (double)s2
                  - 2.0 * (double)s1 * (double)a1
                  + (double)N * (double)a2;
        }
    }
    if (tid == 0) g_ar_partial[abid] = part;
}

// ---------------- kernels ----------------
__global__ __launch_bounds__(256) void phiT_kernel(const float* __restrict__ Phi) {
    __shared__ float tile[32][33];
    const int k  = blockIdx.z;
    const int nb = blockIdx.y * 32;
    const int mb = blockIdx.x * 32;
    const int tx = threadIdx.x & 31;
    const int ty = threadIdx.x >> 5;           // 0..7

    const float* src = Phi + (k << 16);
    #pragma unroll
    for (int r = 0; r < 4; ++r)
        tile[ty + r * 8][tx] = src[(nb + ty + r * 8) * N + mb + tx];
    __syncthreads();

    float* dst = g_phiT + (k << 16);
    #pragma unroll
    for (int r = 0; r < 4; ++r)
        dst[(mb + ty + r * 8) * N + nb + tx] = tile[tx][ty + r * 8];
}

__global__ __launch_bounds__(256, 4) void mega_kernel(const float* __restrict__ Z,
                                                      const float* __restrict__ W,
                                                      const float* __restrict__ alpha) {
    __shared__ SmemU sm;
    int bid = blockIdx.x;
    // AR blocks FIRST: FMA-bound CTAs live in wave 1, overlapping the
    // memory-bound btl blocks instead of forming a serial tail.
    if (bid < AR_BLOCKS) ar_block(alpha, sm.a, bid);
    else                 btl_block(Z, W, alpha, sm.b, bid - AR_BLOCKS);
}

__global__ __launch_bounds__(256) void finalize_kernel(float* __restrict__ out) {
    __shared__ double sd[256];
    const int tid = threadIdx.x;

    double s = 0.0;
    for (int i = tid; i < BTL_BLOCKS; i += 256) s += (double)g_btl_partial[i];
    sd[tid] = s;
    __syncthreads();
    #pragma unroll
    for (int o = 128; o > 0; o >>= 1) {
        if (tid < o) sd[tid] += sd[tid + o];
        __syncthreads();
    }
    if (tid == 0) out[0] = (float)sd[0];
    __syncthreads();

    s = 0.0;
    for (int i = tid; i < AR_BLOCKS; i += 256) s += g_ar_partial[i];
    sd[tid] = s;
    __syncthreads();
    #pragma unroll
    for (int o = 128; o > 0; o >>= 1) {
        if (tid < o) sd[tid] += sd[tid + o];
        __syncthreads();
    }
    if (tid == 0) out[1] = (float)sd[0];
}

extern "C" void kernel_launch(void* const* d_in, const int* in_sizes, int n_in,
                              void* d_out, int out_size) {
    const float* Z     = (const float*)d_in[0];
    const float* W     = (const float*)d_in[1];
    const float* Phi   = (const float*)d_in[2];
    const float* alpha = (const float*)d_in[3];
    float* out = (float*)d_out;

    phiT_kernel<<<dim3(8, 8, 4), 256>>>(Phi);
    mega_kernel<<<TOTAL_BLOCKS, 256>>>(Z, W, alpha);
    finalize_kernel<<<1, 256>>>(out);
}

// round 6
// speedup vs baseline: 1.0396x; 1.0396x over previous
#include <cuda_runtime.h>
#include <cstdint>

#define DEV_INLINE __device__ __forceinline__

constexpr int N  = 256;
constexpr int T  = 1024;
constexpr int P  = 4;
constexpr int AS = T + P;        // alpha row stride = 1028 floats (16B-aligned rows)
constexpr int Tp = T - P;        // 1020

// ---- btl: linear-sweep blocks, block = (i, 8-j-group) x full t ----
// blocks per i: 32 - ((i+1)>>3); total = 4192
constexpr int BTL_BLOCKS = 4192;

// ---- ar tiling ----
constexpr int AR_TT     = 8;
constexpr int AR_BLOCKS = (Tp + AR_TT - 1) / AR_TT; // 128

constexpr int TOTAL_BLOCKS = BTL_BLOCKS + AR_BLOCKS; // 4320

__device__ float  g_btl_partial[BTL_BLOCKS];
__device__ double g_ar_partial[AR_BLOCKS];
__device__ float  g_phiT[P * N * N];  // PhiT[k][m][n]

struct SmemBTL {
    float red[8];
};
struct SmemAR {
    float sa[N][AR_TT + P];
    float red[8];
};
union SmemU { SmemBTL b; SmemAR a; };

DEV_INLINE float warpReduce(float v) {
    #pragma unroll
    for (int o = 16; o > 0; o >>= 1)
        v += __shfl_xor_sync(0xffffffffu, v, o);
    return v;
}

DEV_INLINE float blockReduce(float v, float* red) {
    v = warpReduce(v);
    if ((threadIdx.x & 31) == 0) red[threadIdx.x >> 5] = v;
    __syncthreads();
    float r = 0.f;
    if (threadIdx.x < 32) {
        r = (threadIdx.x < 8) ? red[threadIdx.x] : 0.f;
        #pragma unroll
        for (int o = 4; o > 0; o >>= 1)
            r += __shfl_xor_sync(0xffffffffu, r, o);
    }
    __syncthreads();
    return r;
}

// prefix count of btl blocks before row i (analytic, no memory)
DEV_INLINE int btl_cum(int i) {
    int m = i >> 3;
    return 32 * i - (4 * m * (m - 1) + (i - 8 * m + 1) * m);
}

DEV_INLINE float4 exp4(float4 v) {
    return make_float4(__expf(v.x), __expf(v.y), __expf(v.z), __expf(v.w));
}

// ---------------- BTL part: block = (i, j0..j0+7) x t=0..1023 ----------------
DEV_INLINE void btl_block(const float* __restrict__ Z,
                          const float* __restrict__ W,
                          const float* __restrict__ alpha,
                          SmemBTL& s, int bid) {
    // bid -> (i, jg) via 8-step binary search on analytic prefix
    int i = 0;
    #pragma unroll
    for (int step = 128; step > 0; step >>= 1) {
        int cand = i + step;
        if (cand <= 255 && btl_cum(cand) <= bid) i = cand;
    }
    const int jg = ((i + 1) >> 3) + (bid - btl_cum(i));
    const int j0 = jg * 8;
    const bool partial = (j0 <= i);   // group straddles the diagonal

    const int tid = threadIdx.x;      // t0 = 4*tid (float4 per thread, full t range)

    const float4* a4 = (const float4*)(alpha);
    // alpha row r, t block: element offset r*AS + P + 4*tid -> float4 idx (r*AS+P)/4 + tid
    const float4 si4 = a4[(i * AS + P) / 4 + tid];
    const float4 ei4 = exp4(si4);

    const float4* Z4 = (const float4*)Z;
    const float4* W4 = (const float4*)W;
    const size_t rowbase = (size_t)(i * N + j0) * (T / 4) + tid;

    float acc0 = 0.f, acc1 = 0.f;

    #pragma unroll
    for (int h = 0; h < 2; ++h) {
        const int jb = h * 4;

        // stage alpha_j for 4 rows
        float4 sj4[4], ej4[4];
        #pragma unroll
        for (int r = 0; r < 4; ++r)
            sj4[r] = a4[((j0 + jb + r) * AS + P) / 4 + tid];
        #pragma unroll
        for (int r = 0; r < 4; ++r)
            ej4[r] = exp4(sj4[r]);

        // batched Z loads (4 x 16B, address-ordered)
        float4 z4[4];
        #pragma unroll
        for (int r = 0; r < 4; ++r)
            z4[r] = Z4[rowbase + (size_t)(jb + r) * (T / 4)];

        // lse per row (ej dies into lse)
        float4 lse[4];
        #pragma unroll
        for (int r = 0; r < 4; ++r) {
            lse[r].x = __logf(ei4.x + ej4[r].x);
            lse[r].y = __logf(ei4.y + ej4[r].y);
            lse[r].z = __logf(ei4.z + ej4[r].z);
            lse[r].w = __logf(ei4.w + ej4[r].w);
        }

        // batched W loads
        float4 w4[4];
        #pragma unroll
        for (int r = 0; r < 4; ++r)
            w4[r] = W4[rowbase + (size_t)(jb + r) * (T / 4)];

        if (partial) {   // uniform branch: zero out rows with j <= i
            #pragma unroll
            for (int r = 0; r < 4; ++r) {
                float m = (j0 + jb + r > i) ? 1.f : 0.f;
                z4[r].x *= m; z4[r].y *= m; z4[r].z *= m; z4[r].w *= m;
                w4[r].x *= m; w4[r].y *= m; w4[r].z *= m; w4[r].w *= m;
            }
        }

        #pragma unroll
        for (int r = 0; r < 4; ++r) {
            acc0 = fmaf(z4[r].x, si4.x - lse[r].x, acc0);
            acc0 = fmaf(z4[r].y, si4.y - lse[r].y, acc0);
            acc0 = fmaf(z4[r].z, si4.z - lse[r].z, acc0);
            acc0 = fmaf(z4[r].w, si4.w - lse[r].w, acc0);
            acc1 = fmaf(w4[r].x, sj4[r].x - lse[r].x, acc1);
            acc1 = fmaf(w4[r].y, sj4[r].y - lse[r].y, acc1);
            acc1 = fmaf(w4[r].z, sj4[r].z - lse[r].z, acc1);
            acc1 = fmaf(w4[r].w, sj4[r].w - lse[r].w, acc1);
        }
    }

    float tot = blockReduce(acc0 + acc1, s.red);
    if (tid == 0) g_btl_partial[bid] = tot;
}

// ---------------- AR part (proven, unchanged) ----------------
DEV_INLINE void ar_block(const float* __restrict__ alpha,
                         SmemAR& s, int abid) {
    const int t0  = abid * AR_TT;
    const int tid = threadIdx.x;   // = n

    #pragma unroll
    for (int c = 0; c < AR_TT + P; ++c)
        s.sa[tid][c] = alpha[tid * AS + t0 + c];
    __syncthreads();

    float acc[AR_TT];
    #pragma unroll
    for (int tt = 0; tt < AR_TT; ++tt) acc[tt] = 0.f;

    #pragma unroll 2
    for (int m = 0; m < N; ++m) {
        float av[AR_TT + P];
        #pragma unroll
        for (int c = 0; c < AR_TT + P; ++c) av[c] = s.sa[m][c];
        #pragma unroll
        for (int k = 0; k < P; ++k) {
            float phi = g_phiT[((k * N) + m) * N + tid]; // coalesced over tid
            #pragma unroll
            for (int tt = 0; tt < AR_TT; ++tt)
                acc[tt] = fmaf(phi, av[k + tt], acc[tt]);
        }
    }

    // sum_{n,n2} (S_n - A_n2)^2 = N*sum S^2 - 2*(sum S)(sum A) + N*sum A^2
    double part = 0.0;
    #pragma unroll 1
    for (int tt = 0; tt < AR_TT; ++tt) {
        float S = acc[tt];
        float A = s.sa[tid][tt + P];
        float s1 = blockReduce(S, s.red);
        float s2 = blockReduce(S * S, s.red);
        float a1 = blockReduce(A, s.red);
        float a2 = blockReduce(A * A, s.red);
        if (tid == 0 && (t0 + tt) < Tp) {
            part += (double)N * (double)s2
                  - 2.0 * (double)s1 * (double)a1
                  + (double)N * (double)a2;
        }
    }
    if (tid == 0) g_ar_partial[abid] = part;
}

// ---------------- kernels ----------------
__global__ __launch_bounds__(256) void phiT_kernel(const float* __restrict__ Phi) {
    __shared__ float tile[32][33];
    const int k  = blockIdx.z;
    const int nb = blockIdx.y * 32;
    const int mb = blockIdx.x * 32;
    const int tx = threadIdx.x & 31;
    const int ty = threadIdx.x >> 5;           // 0..7

    const float* src = Phi + (k << 16);
    #pragma unroll
    for (int r = 0; r < 4; ++r)
        tile[ty + r * 8][tx] = src[(nb + ty + r * 8) * N + mb + tx];
    __syncthreads();

    float* dst = g_phiT + (k << 16);
    #pragma unroll
    for (int r = 0; r < 4; ++r)
        dst[(mb + ty + r * 8) * N + nb + tx] = tile[tx][ty + r * 8];
}

__global__ __launch_bounds__(256, 3) void mega_kernel(const float* __restrict__ Z,
                                                      const float* __restrict__ W,
                                                      const float* __restrict__ alpha) {
    __shared__ SmemU sm;
    int bid = blockIdx.x;
    // AR blocks FIRST: FMA-bound CTAs live in wave 1, overlapping the
    // memory-bound btl sweep instead of forming a serial tail.
    if (bid < AR_BLOCKS) ar_block(alpha, sm.a, bid);
    else                 btl_block(Z, W, alpha, sm.b, bid - AR_BLOCKS);
}

__global__ __launch_bounds__(256) void finalize_kernel(float* __restrict__ out) {
    __shared__ double sd[256];
    const int tid = threadIdx.x;

    // btl: 4192 floats, vectorized float4 reads (4192 % 4 == 0)
    const float4* p4 = (const float4*)g_btl_partial;
    double s = 0.0;
    #pragma unroll 1
    for (int i = tid; i < BTL_BLOCKS / 4; i += 256) {
        float4 v = p4[i];
        s += (double)((v.x + v.y) + (v.z + v.w));
    }
    sd[tid] = s;
    __syncthreads();
    #pragma unroll
    for (int o = 128; o > 0; o >>= 1) {
        if (tid < o) sd[tid] += sd[tid + o];
        __syncthreads();
    }
    if (tid == 0) out[0] = (float)sd[0];
    __syncthreads();

    s = 0.0;
    if (tid < AR_BLOCKS) s = g_ar_partial[tid];
    sd[tid] = s;
    __syncthreads();
    #pragma unroll
    for (int o = 128; o > 0; o >>= 1) {
        if (tid < o) sd[tid] += sd[tid + o];
        __syncthreads();
    }
    if (tid == 0) out[1] = (float)sd[0];
}

extern "C" void kernel_launch(void* const* d_in, const int* in_sizes, int n_in,
                              void* d_out, int out_size) {
    const float* Z     = (const float*)d_in[0];
    const float* W     = (const float*)d_in[1];
    const float* Phi   = (const float*)d_in[2];
    const float* alpha = (const float*)d_in[3];
    float* out = (float*)d_out;

    phiT_kernel<<<dim3(8, 8, 4), 256>>>(Phi);
    mega_kernel<<<TOTAL_BLOCKS, 256>>>(Z, W, alpha);
    finalize_kernel<<<1, 256>>>(out);
}

// round 8
// speedup vs baseline: 1.0687x; 1.0280x over previous
#include <cuda_runtime.h>
#include <cstdint>

#define DEV_INLINE __device__ __forceinline__

constexpr int N  = 256;
constexpr int T  = 1024;
constexpr int P  = 4;
constexpr int AS = T + P;        // alpha row stride = 1028 floats
constexpr int Tp = T - P;        // 1020

// ---- btl: linear-sweep blocks, block = (i, 8-j-group) x full t ----
constexpr int BTL_BLOCKS = 4192;
constexpr int BTL_HALF   = BTL_BLOCKS / 2;      // 2096

// ---- ar tiling ----
constexpr int AR_TT     = 8;
constexpr int AR_BLOCKS = (Tp + AR_TT - 1) / AR_TT; // 128

constexpr int PHI_BLOCKS = 256;                  // 8x8x4 transpose tiles

__device__ float  g_btl_partial[BTL_BLOCKS];
__device__ double g_ar_partial[AR_BLOCKS];
__device__ float  g_phiT[P * N * N];  // PhiT[k][m][n]

struct SmemBTL {
    float red[8];
};
struct SmemAR {
    float sa[N][AR_TT + P];
    float red[8];
};
struct SmemPhi {
    float tile[32][33];
};
union SmemU { SmemBTL b; SmemAR a; SmemPhi p; };

DEV_INLINE float warpReduce(float v) {
    #pragma unroll
    for (int o = 16; o > 0; o >>= 1)
        v += __shfl_xor_sync(0xffffffffu, v, o);
    return v;
}

DEV_INLINE float blockReduce(float v, float* red) {
    v = warpReduce(v);
    if ((threadIdx.x & 31) == 0) red[threadIdx.x >> 5] = v;
    __syncthreads();
    float r = 0.f;
    if (threadIdx.x < 32) {
        r = (threadIdx.x < 8) ? red[threadIdx.x] : 0.f;
        #pragma unroll
        for (int o = 4; o > 0; o >>= 1)
            r += __shfl_xor_sync(0xffffffffu, r, o);
    }
    __syncthreads();
    return r;
}

// prefix count of btl blocks before row i (analytic, no memory)
DEV_INLINE int btl_cum(int i) {
    int m = i >> 3;
    return 32 * i - (4 * m * (m - 1) + (i - 8 * m + 1) * m);
}

DEV_INLINE float4 exp4(float4 v) {
    return make_float4(__expf(v.x), __expf(v.y), __expf(v.z), __expf(v.w));
}

// ---------------- BTL: block = (i, j0..j0+7) x t=0..1023, j processed in pairs ----
DEV_INLINE void btl_block(const float* __restrict__ Z,
                          const float* __restrict__ W,
                          const float* __restrict__ alpha,
                          SmemBTL& s, int bid) {
    // bid -> (i, jg) via 8-step binary search on analytic prefix
    int i = 0;
    #pragma unroll
    for (int step = 128; step > 0; step >>= 1) {
        int cand = i + step;
        if (cand <= 255 && btl_cum(cand) <= bid) i = cand;
    }
    const int jg = ((i + 1) >> 3) + (bid - btl_cum(i));
    const int j0 = jg * 8;
    const bool partial = (j0 <= i);   // group straddles the diagonal

    const int tid = threadIdx.x;      // 4 t's per thread (float4), full t range

    const float4* a4 = (const float4*)(alpha);
    const float4 si4 = a4[(i * AS + P) / 4 + tid];
    const float4 ei4 = exp4(si4);

    const float4* Z4 = (const float4*)Z;
    const float4* W4 = (const float4*)W;
    const size_t rowbase = (size_t)(i * N + j0) * (T / 4) + tid;

    float acc0 = 0.f, acc1 = 0.f;

    #pragma unroll
    for (int jb = 0; jb < 8; jb += 2) {
        float4 sjA = a4[((j0 + jb)     * AS + P) / 4 + tid];
        float4 sjB = a4[((j0 + jb + 1) * AS + P) / 4 + tid];

        // independent streaming loads (read-once: evict-first)
        float4 zA = __ldcs(Z4 + rowbase + (size_t)(jb)     * (T / 4));
        float4 zB = __ldcs(Z4 + rowbase + (size_t)(jb + 1) * (T / 4));
        float4 wA = __ldcs(W4 + rowbase + (size_t)(jb)     * (T / 4));
        float4 wB = __ldcs(W4 + rowbase + (size_t)(jb + 1) * (T / 4));

        float4 lA, lB;
        lA.x = __logf(ei4.x + __expf(sjA.x));
        lA.y = __logf(ei4.y + __expf(sjA.y));
        lA.z = __logf(ei4.z + __expf(sjA.z));
        lA.w = __logf(ei4.w + __expf(sjA.w));
        lB.x = __logf(ei4.x + __expf(sjB.x));
        lB.y = __logf(ei4.y + __expf(sjB.y));
        lB.z = __logf(ei4.z + __expf(sjB.z));
        lB.w = __logf(ei4.w + __expf(sjB.w));

        if (partial) {   // uniform branch: zero rows with j <= i
            float mA = (j0 + jb     > i) ? 1.f : 0.f;
            float mB = (j0 + jb + 1 > i) ? 1.f : 0.f;
            zA.x *= mA; zA.y *= mA; zA.z *= mA; zA.w *= mA;
            wA.x *= mA; wA.y *= mA; wA.z *= mA; wA.w *= mA;
            zB.x *= mB; zB.y *= mB; zB.z *= mB; zB.w *= mB;
            wB.x *= mB; wB.y *= mB; wB.z *= mB; wB.w *= mB;
        }

        acc0 = fmaf(zA.x, si4.x - lA.x, acc0);
        acc0 = fmaf(zA.y, si4.y - lA.y, acc0);
        acc0 = fmaf(zA.z, si4.z - lA.z, acc0);
        acc0 = fmaf(zA.w, si4.w - lA.w, acc0);
        acc1 = fmaf(wA.x, sjA.x - lA.x, acc1);
        acc1 = fmaf(wA.y, sjA.y - lA.y, acc1);
        acc1 = fmaf(wA.z, sjA.z - lA.z, acc1);
        acc1 = fmaf(wA.w, sjA.w - lA.w, acc1);
        acc0 = fmaf(zB.x, si4.x - lB.x, acc0);
        acc0 = fmaf(zB.y, si4.y - lB.y, acc0);
        acc0 = fmaf(zB.z, si4.z - lB.z, acc0);
        acc0 = fmaf(zB.w, si4.w - lB.w, acc0);
        acc1 = fmaf(wB.x, sjB.x - lB.x, acc1);
        acc1 = fmaf(wB.y, sjB.y - lB.y, acc1);
        acc1 = fmaf(wB.z, sjB.z - lB.z, acc1);
        acc1 = fmaf(wB.w, sjB.w - lB.w, acc1);
    }

    float tot = blockReduce(acc0 + acc1, s.red);
    if (tid == 0) g_btl_partial[bid] = tot;
}

// ---------------- AR part (proven, unchanged) ----------------
DEV_INLINE void ar_block(const float* __restrict__ alpha,
                         SmemAR& s, int abid) {
    const int t0  = abid * AR_TT;
    const int tid = threadIdx.x;   // = n

    #pragma unroll
    for (int c = 0; c < AR_TT + P; ++c)
        s.sa[tid][c] = alpha[tid * AS + t0 + c];
    __syncthreads();

    float acc[AR_TT];
    #pragma unroll
    for (int tt = 0; tt < AR_TT; ++tt) acc[tt] = 0.f;

    #pragma unroll 2
    for (int m = 0; m < N; ++m) {
        float av[AR_TT + P];
        #pragma unroll
        for (int c = 0; c < AR_TT + P; ++c) av[c] = s.sa[m][c];
        #pragma unroll
        for (int k = 0; k < P; ++k) {
            float phi = g_phiT[((k * N) + m) * N + tid]; // coalesced over tid
            #pragma unroll
            for (int tt = 0; tt < AR_TT; ++tt)
                acc[tt] = fmaf(phi, av[k + tt], acc[tt]);
        }
    }

    double part = 0.0;
    #pragma unroll 1
    for (int tt = 0; tt < AR_TT; ++tt) {
        float S = acc[tt];
        float A = s.sa[tid][tt + P];
        float s1 = blockReduce(S, s.red);
        float s2 = blockReduce(S * S, s.red);
        float a1 = blockReduce(A, s.red);
        float a2 = blockReduce(A * A, s.red);
        if (tid == 0 && (t0 + tt) < Tp) {
            part += (double)N * (double)s2
                  - 2.0 * (double)s1 * (double)a1
                  + (double)N * (double)a2;
        }
    }
    if (tid == 0) g_ar_partial[abid] = part;
}

// ---------------- Phi transpose block (inside K1) ----------------
DEV_INLINE void phiT_block(const float* __restrict__ Phi, SmemPhi& s, int b) {
    const int k  = b >> 6;
    const int r6 = b & 63;
    const int nb = (r6 >> 3) * 32;
    const int mb = (r6 & 7) * 32;
    const int tx = threadIdx.x & 31;
    const int ty = threadIdx.x >> 5;           // 0..7

    const float* src = Phi + (k << 16);
    #pragma unroll
    for (int r = 0; r < 4; ++r)
        s.tile[ty + r * 8][tx] = src[(nb + ty + r * 8) * N + mb + tx];
    __syncthreads();

    float* dst = g_phiT + (k << 16);
    #pragma unroll
    for (int r = 0; r < 4; ++r)
        dst[(mb + ty + r * 8) * N + nb + tx] = s.tile[tx][ty + r * 8];
}

// ---------------- kernels ----------------
// K1: phiT transpose + first half of btl (btl never reads g_phiT -> safe)
__global__ __launch_bounds__(256, 4) void mega_kernel_a(const float* __restrict__ Z,
                                                        const float* __restrict__ W,
                                                        const float* __restrict__ alpha,
                                                        const float* __restrict__ Phi) {
    __shared__ SmemU sm;
    int bid = blockIdx.x;
    if (bid < PHI_BLOCKS) phiT_block(Phi, sm.p, bid);
    else                  btl_block(Z, W, alpha, sm.b, bid - PHI_BLOCKS);
}

// K2: AR blocks (read g_phiT from K1) + second half of btl
__global__ __launch_bounds__(256, 4) void mega_kernel_b(const float* __restrict__ Z,
                                                        const float* __restrict__ W,
                                                        const float* __restrict__ alpha) {
    __shared__ SmemU sm;
    int bid = blockIdx.x;
    if (bid < AR_BLOCKS) ar_block(alpha, sm.a, bid);
    else                 btl_block(Z, W, alpha, sm.b, BTL_HALF + (bid - AR_BLOCKS));
}

__global__ __launch_bounds__(256) void finalize_kernel(float* __restrict__ out) {
    __shared__ double sd[256];
    const int tid = threadIdx.x;

    const float4* p4 = (const float4*)g_btl_partial;
    double s = 0.0;
    #pragma unroll 1
    for (int i = tid; i < BTL_BLOCKS / 4; i += 256) {
        float4 v = p4[i];
        s += (double)((v.x + v.y) + (v.z + v.w));
    }
    sd[tid] = s;
    __syncthreads();
    #pragma unroll
    for (int o = 128; o > 0; o >>= 1) {
        if (tid < o) sd[tid] += sd[tid + o];
        __syncthreads();
    }
    if (tid == 0) out[0] = (float)sd[0];
    __syncthreads();

    s = 0.0;
    if (tid < AR_BLOCKS) s = g_ar_partial[tid];
    sd[tid] = s;
    __syncthreads();
    #pragma unroll
    for (int o = 128; o > 0; o >>= 1) {
        if (tid < o) sd[tid] += sd[tid + o];
        __syncthreads();
    }
    if (tid == 0) out[1] = (float)sd[0];
}

extern "C" void kernel_launch(void* const* d_in, const int* in_sizes, int n_in,
                              void* d_out, int out_size) {
    const float* Z     = (const float*)d_in[0];
    const float* W     = (const float*)d_in[1];
    const float* Phi   = (const float*)d_in[2];
    const float* alpha = (const float*)d_in[3];
    float* out = (float*)d_out;

    mega_kernel_a<<<PHI_BLOCKS + BTL_HALF, 256>>>(Z, W, alpha, Phi);
    mega_kernel_b<<<AR_BLOCKS + BTL_HALF, 256>>>(Z, W, alpha);
    finalize_kernel<<<1, 256>>>(out);
}